// round 2
// baseline (speedup 1.0000x reference)
#include <cuda_runtime.h>

#define BATCH 8
#define CH    128
#define HH    112
#define WW    112
#define HWSZ  12544     // 112*112
#define NH    4
#define HD    32
#define KS    7
#define KK2   49
#define SCALE 0.17677669529663687f   // 32^-0.5

// Scratch (static device allocations; no cudaMalloc allowed).
// __align__(16): these are accessed via float4 casts.
static __device__ __align__(16) float g_q  [BATCH*NH*HWSZ*HD];   // (b,h,p,d)
static __device__ __align__(16) float g_k  [BATCH*NH*HWSZ*HD];
static __device__ __align__(16) float g_v  [BATCH*NH*HWSZ*HD];
static __device__ __align__(16) float g_dot[BATCH*NH*HWSZ];      // (b,h,p)
static __device__ __align__(16) float g_att[BATCH*HWSZ*CH];      // (b,p,c)  c = h*32+d

// ------------------------------------------------------------------
// Kernel 1: QKV GEMM.  qkv[m,n] = sum_k x[b,k,hw] * W[n,k] + bias[n]
// M = 100352 (b*HW+hw), N = 384, K = 128.
// Block tile 128x128, BK=16, 256 threads, 8x8 microtile.
// Epilogue writes q/k/v in (b, head, pixel, d) layout.
// ------------------------------------------------------------------
__global__ __launch_bounds__(256) void qkv_kernel(
    const float* __restrict__ x, const float* __restrict__ wq,
    const float* __restrict__ bias)
{
    __shared__ __align__(16) float As[16][128];
    __shared__ __align__(16) float Bs[16][132];

    const int mtile = blockIdx.y;            // 0..783
    const int n0    = blockIdx.x * 128;      // 0,128,256
    const int b     = mtile / 98;            // 12544/128 = 98 exact
    const int hw0   = (mtile - b*98) * 128;
    const int tid   = threadIdx.x;
    const int tx    = tid & 15, ty = tid >> 4;
    const int ln    = tid >> 1;              // 0..127 (B-tile row)
    const int lk    = (tid & 1) * 8;         // 0 or 8

    const float* xb = x + (size_t)b * (CH*HWSZ) + hw0;

    float acc[8][8];
#pragma unroll
    for (int i = 0; i < 8; ++i)
#pragma unroll
        for (int j = 0; j < 8; ++j) acc[i][j] = 0.f;

    for (int kk0 = 0; kk0 < CH; kk0 += 16) {
        // A tile: As[k][m], coalesced along m (hw contiguous in x)
#pragma unroll
        for (int u = 0; u < 8; ++u) {
            int idx = tid + u * 256;
            int mm = idx & 127, kk = idx >> 7;
            As[kk][mm] = xb[(kk0 + kk) * HWSZ + mm];
        }
        // B tile: Bs[k][n] from W[n,k] (k contiguous -> float4, transpose in smem)
        {
            const float* wp = wq + (size_t)(n0 + ln) * CH + kk0 + lk;
            float4 w0 = *(const float4*)wp;
            float4 w1 = *(const float4*)(wp + 4);
            Bs[lk+0][ln] = w0.x; Bs[lk+1][ln] = w0.y;
            Bs[lk+2][ln] = w0.z; Bs[lk+3][ln] = w0.w;
            Bs[lk+4][ln] = w1.x; Bs[lk+5][ln] = w1.y;
            Bs[lk+6][ln] = w1.z; Bs[lk+7][ln] = w1.w;
        }
        __syncthreads();
#pragma unroll
        for (int k = 0; k < 16; ++k) {
            float a[8], bb[8];
            *(float4*)&a[0]  = *(const float4*)&As[k][tx*4];
            *(float4*)&a[4]  = *(const float4*)&As[k][64 + tx*4];
            *(float4*)&bb[0] = *(const float4*)&Bs[k][ty*4];
            *(float4*)&bb[4] = *(const float4*)&Bs[k][64 + ty*4];
#pragma unroll
            for (int i = 0; i < 8; ++i)
#pragma unroll
                for (int j = 0; j < 8; ++j) acc[i][j] += a[i] * bb[j];
        }
        __syncthreads();
    }

    // Epilogue: n0 picks type (q/k/v) since tiles align to 128.
    const int type = n0 >> 7;
    float* dst = (type == 0) ? g_q : (type == 1) ? g_k : g_v;
#pragma unroll
    for (int jh = 0; jh < 2; ++jh) {
        int cw = jh * 64 + ty * 4;           // channel within type block
        int h  = cw >> 5, d = cw & 31;       // float4 stays inside one head
        float4 bi = *(const float4*)&bias[n0 + cw];
        float* hb = dst + (size_t)(b * NH + h) * (HWSZ * HD) + d;
#pragma unroll
        for (int ih = 0; ih < 2; ++ih) {
#pragma unroll
            for (int i2 = 0; i2 < 4; ++i2) {
                int i   = ih * 4 + i2;
                int pix = hw0 + ih * 64 + tx * 4 + i2;
                float4 o;
                o.x = acc[i][jh*4+0] + bi.x;
                o.y = acc[i][jh*4+1] + bi.y;
                o.z = acc[i][jh*4+2] + bi.z;
                o.w = acc[i][jh*4+3] + bi.w;
                *(float4*)&hb[(size_t)pix * HD] = o;
            }
        }
    }
}

// ------------------------------------------------------------------
// Kernel 2: dot[b,h,p] = SCALE * sum_d q[b,h,p,d]*k[b,h,p,d]
// 4 threads per pixel (8 floats each), shfl reduce.
// ------------------------------------------------------------------
__global__ __launch_bounds__(256) void dot_kernel()
{
    const int bh = blockIdx.y;                       // 0..31
    const int t  = blockIdx.x * 256 + threadIdx.x;   // 0..50175
    const int p    = t >> 2;
    const int part = t & 3;
    const int base = (bh * HWSZ + p) * HD + part * 8;
    float4 q1 = *(const float4*)&g_q[base];
    float4 q2 = *(const float4*)&g_q[base + 4];
    float4 k1 = *(const float4*)&g_k[base];
    float4 k2 = *(const float4*)&g_k[base + 4];
    float s = q1.x*k1.x + q1.y*k1.y + q1.z*k1.z + q1.w*k1.w
            + q2.x*k2.x + q2.y*k2.y + q2.z*k2.z + q2.w*k2.w;
    s += __shfl_xor_sync(0xffffffffu, s, 1);
    s += __shfl_xor_sync(0xffffffffu, s, 2);
    if (part == 0) g_dot[bh * HWSZ + p] = s * SCALE;
}

// ------------------------------------------------------------------
// Kernel 3: neighborhood attention (circular).
// One block = 16x16 output pixels for one (b,h). Window = 22x22.
// dot-window + rpb in smem; v-window in two 16-channel halves (48KB limit).
// 49 softmax weights live in registers.
// vs stride 20 floats -> conflict-free float4 LDS.
// ------------------------------------------------------------------
__global__ __launch_bounds__(256) void attn_kernel(const float* __restrict__ rpb)
{
    __shared__ __align__(16) float ds[22 * 24];
    __shared__ __align__(16) float rs[KK2];
    __shared__ __align__(16) float vs[484 * 20];

    const int bh = blockIdx.z;        // b*4 + h
    const int h  = bh & 3;
    const int b  = bh >> 2;
    const int y0 = blockIdx.y * 16;
    const int x0 = blockIdx.x * 16;
    const int tid = threadIdx.x;

    // dot window (wrapped)
    for (int idx = tid; idx < 484; idx += 256) {
        int r  = idx / 22, cc = idx - r * 22;
        int gy = y0 + r;  if (gy >= HH) gy -= HH;
        int gx = x0 + cc; if (gx >= WW) gx -= WW;
        ds[r * 24 + cc] = g_dot[bh * HWSZ + gy * WW + gx];
    }
    if (tid < KK2) rs[tid] = rpb[h * KK2 + tid];

    const float* vbase = g_v + (size_t)bh * (HWSZ * HD);

    // v window, channels 0..15
    for (int idx = tid; idx < 484 * 4; idx += 256) {
        int pix = idx >> 2, g = idx & 3;
        int r  = pix / 22, cc = pix - r * 22;
        int gy = y0 + r;  if (gy >= HH) gy -= HH;
        int gx = x0 + cc; if (gx >= WW) gx -= WW;
        *(float4*)&vs[pix * 20 + g * 4] =
            *(const float4*)&vbase[(size_t)(gy * WW + gx) * HD + g * 4];
    }
    __syncthreads();

    const int ty = tid >> 4, tx = tid & 15;

    // softmax weights
    float w[KK2];
    float mx = -1e30f;
#pragma unroll
    for (int i = 0; i < 7; ++i)
#pragma unroll
        for (int j = 0; j < 7; ++j) {
            float val = ds[(ty + i) * 24 + tx + j] + rs[i * 7 + j];
            w[i * 7 + j] = val;
            mx = fmaxf(mx, val);
        }
    float sum = 0.f;
#pragma unroll
    for (int n = 0; n < KK2; ++n) { w[n] = __expf(w[n] - mx); sum += w[n]; }
    const float inv = 1.f / sum;

    const int p = (y0 + ty) * WW + (x0 + tx);
    float* obase = g_att + (size_t)(b * HWSZ + p) * CH + h * HD;

    // channels 0..15
    {
        float4 acc[4];
#pragma unroll
        for (int g = 0; g < 4; ++g) acc[g] = make_float4(0.f, 0.f, 0.f, 0.f);
#pragma unroll
        for (int i = 0; i < 7; ++i)
#pragma unroll
            for (int j = 0; j < 7; ++j) {
                float wt  = w[i * 7 + j];
                int   pix = (ty + i) * 22 + (tx + j);
#pragma unroll
                for (int g = 0; g < 4; ++g) {
                    float4 vv = *(const float4*)&vs[pix * 20 + g * 4];
                    acc[g].x += wt * vv.x; acc[g].y += wt * vv.y;
                    acc[g].z += wt * vv.z; acc[g].w += wt * vv.w;
                }
            }
#pragma unroll
        for (int g = 0; g < 4; ++g) {
            float4 o = make_float4(acc[g].x*inv, acc[g].y*inv, acc[g].z*inv, acc[g].w*inv);
            *(float4*)&obase[g * 4] = o;
        }
    }
    __syncthreads();

    // v window, channels 16..31
    for (int idx = tid; idx < 484 * 4; idx += 256) {
        int pix = idx >> 2, g = idx & 3;
        int r  = pix / 22, cc = pix - r * 22;
        int gy = y0 + r;  if (gy >= HH) gy -= HH;
        int gx = x0 + cc; if (gx >= WW) gx -= WW;
        *(float4*)&vs[pix * 20 + g * 4] =
            *(const float4*)&vbase[(size_t)(gy * WW + gx) * HD + 16 + g * 4];
    }
    __syncthreads();

    {
        float4 acc[4];
#pragma unroll
        for (int g = 0; g < 4; ++g) acc[g] = make_float4(0.f, 0.f, 0.f, 0.f);
#pragma unroll
        for (int i = 0; i < 7; ++i)
#pragma unroll
            for (int j = 0; j < 7; ++j) {
                float wt  = w[i * 7 + j];
                int   pix = (ty + i) * 22 + (tx + j);
#pragma unroll
                for (int g = 0; g < 4; ++g) {
                    float4 vv = *(const float4*)&vs[pix * 20 + g * 4];
                    acc[g].x += wt * vv.x; acc[g].y += wt * vv.y;
                    acc[g].z += wt * vv.z; acc[g].w += wt * vv.w;
                }
            }
#pragma unroll
        for (int g = 0; g < 4; ++g) {
            float4 o = make_float4(acc[g].x*inv, acc[g].y*inv, acc[g].z*inv, acc[g].w*inv);
            *(float4*)&obase[16 + g * 4] = o;
        }
    }
}

// ------------------------------------------------------------------
// Kernel 4: proj GEMM + transpose to (B,C,H,W).
// out[b,n,hw] = sum_k g_att[m,k] * pw[n,k] + pb[n],  m = b*HW+hw.
// Block tile 128x128 (N=128 -> single n-tile), BK=16, 8x8 microtile.
// Stores are m-contiguous float4 (coalesced channels-first writes).
// ------------------------------------------------------------------
__global__ __launch_bounds__(256) void proj_kernel(
    const float* __restrict__ pw, const float* __restrict__ pb,
    float* __restrict__ out)
{
    __shared__ __align__(16) float As[16][132];
    __shared__ __align__(16) float Bs[16][132];

    const int mtile = blockIdx.x;            // 0..783
    const int m0    = mtile * 128;
    const int tid   = threadIdx.x;
    const int tx    = tid & 15, ty = tid >> 4;
    const int ln    = tid >> 1;
    const int lk    = (tid & 1) * 8;

    float acc[8][8];
#pragma unroll
    for (int i = 0; i < 8; ++i)
#pragma unroll
        for (int j = 0; j < 8; ++j) acc[i][j] = 0.f;

    for (int kk0 = 0; kk0 < CH; kk0 += 16) {
        {
            const float* ap = g_att + (size_t)(m0 + ln) * CH + kk0 + lk;
            float4 a0 = *(const float4*)ap;
            float4 a1 = *(const float4*)(ap + 4);
            As[lk+0][ln] = a0.x; As[lk+1][ln] = a0.y;
            As[lk+2][ln] = a0.z; As[lk+3][ln] = a0.w;
            As[lk+4][ln] = a1.x; As[lk+5][ln] = a1.y;
            As[lk+6][ln] = a1.z; As[lk+7][ln] = a1.w;

            const float* wp = pw + (size_t)ln * CH + kk0 + lk;
            float4 w0 = *(const float4*)wp;
            float4 w1 = *(const float4*)(wp + 4);
            Bs[lk+0][ln] = w0.x; Bs[lk+1][ln] = w0.y;
            Bs[lk+2][ln] = w0.z; Bs[lk+3][ln] = w0.w;
            Bs[lk+4][ln] = w1.x; Bs[lk+5][ln] = w1.y;
            Bs[lk+6][ln] = w1.z; Bs[lk+7][ln] = w1.w;
        }
        __syncthreads();
#pragma unroll
        for (int k = 0; k < 16; ++k) {
            float a[8], bb[8];
            *(float4*)&a[0]  = *(const float4*)&As[k][tx*4];
            *(float4*)&a[4]  = *(const float4*)&As[k][64 + tx*4];
            *(float4*)&bb[0] = *(const float4*)&Bs[k][ty*4];
            *(float4*)&bb[4] = *(const float4*)&Bs[k][64 + ty*4];
#pragma unroll
            for (int i = 0; i < 8; ++i)
#pragma unroll
                for (int j = 0; j < 8; ++j) acc[i][j] += a[i] * bb[j];
        }
        __syncthreads();
    }

    const int b   = mtile / 98;
    const int hw0 = (mtile - b * 98) * 128;
#pragma unroll
    for (int jh = 0; jh < 2; ++jh) {
#pragma unroll
        for (int j2 = 0; j2 < 4; ++j2) {
            int n = jh * 64 + ty * 4 + j2;
            float bias = pb[n];
            float* orow = out + (size_t)(b * CH + n) * HWSZ + hw0;
            int j = jh * 4 + j2;
            float4 o0 = make_float4(acc[0][j]+bias, acc[1][j]+bias,
                                    acc[2][j]+bias, acc[3][j]+bias);
            float4 o1 = make_float4(acc[4][j]+bias, acc[5][j]+bias,
                                    acc[6][j]+bias, acc[7][j]+bias);
            *(float4*)&orow[tx * 4]      = o0;
            *(float4*)&orow[64 + tx * 4] = o1;
        }
    }
}

// ------------------------------------------------------------------
extern "C" void kernel_launch(void* const* d_in, const int* in_sizes, int n_in,
                              void* d_out, int out_size)
{
    const float* x      = (const float*)d_in[0];
    const float* qkv_w  = (const float*)d_in[1];
    const float* qkv_b  = (const float*)d_in[2];
    const float* rpb    = (const float*)d_in[3];
    const float* proj_w = (const float*)d_in[4];
    const float* proj_b = (const float*)d_in[5];
    float* out = (float*)d_out;

    qkv_kernel<<<dim3(3, 784), 256>>>(x, qkv_w, qkv_b);
    dot_kernel<<<dim3(196, 32), 256>>>();
    attn_kernel<<<dim3(7, 7, 32), 256>>>(rpb);
    proj_kernel<<<784, 256>>>(proj_w, proj_b, out);
}

// round 3
// speedup vs baseline: 1.3025x; 1.3025x over previous
#include <cuda_runtime.h>
#include <cuda_bf16.h>

#define BATCH 8
#define CH    128
#define HH    112
#define WW    112
#define HWSZ  12544     // 112*112
#define NH    4
#define HD    32
#define KS    7
#define KK2   49
#define SCALE 0.17677669529663687f   // 32^-0.5

// Scratch (static device allocations; no cudaMalloc allowed).
static __device__ __align__(16) float g_q  [BATCH*NH*HWSZ*HD];   // (b,h,p,d)
static __device__ __align__(16) float g_k  [BATCH*NH*HWSZ*HD];
static __device__ __align__(16) float g_v  [BATCH*NH*HWSZ*HD];
static __device__ __align__(16) float g_dot[BATCH*NH*HWSZ];      // (b,h,p)
static __device__ __align__(16) float g_att[BATCH*HWSZ*CH];      // (b,p,c)  c = h*32+d

// ---------------- helpers: bf16 split + ldmatrix + mma -------------

__device__ __forceinline__ unsigned bfpack(__nv_bfloat16 a, __nv_bfloat16 b) {
    return (unsigned)__bfloat16_as_ushort(a) | ((unsigned)__bfloat16_as_ushort(b) << 16);
}

// split float4 -> hi uint2 (4 bf16), lo uint2 (4 bf16)
__device__ __forceinline__ void split4(float4 v, uint2& hi, uint2& lo) {
    __nv_bfloat16 hx = __float2bfloat16(v.x);
    __nv_bfloat16 hy = __float2bfloat16(v.y);
    __nv_bfloat16 hz = __float2bfloat16(v.z);
    __nv_bfloat16 hw = __float2bfloat16(v.w);
    __nv_bfloat16 lx = __float2bfloat16(v.x - __bfloat162float(hx));
    __nv_bfloat16 ly = __float2bfloat16(v.y - __bfloat162float(hy));
    __nv_bfloat16 lz = __float2bfloat16(v.z - __bfloat162float(hz));
    __nv_bfloat16 lw = __float2bfloat16(v.w - __bfloat162float(hw));
    hi.x = bfpack(hx, hy); hi.y = bfpack(hz, hw);
    lo.x = bfpack(lx, ly); lo.y = bfpack(lz, lw);
}

__device__ __forceinline__ void ldsm4(unsigned* r, unsigned addr) {
    asm volatile("ldmatrix.sync.aligned.m8n8.x4.shared.b16 {%0,%1,%2,%3}, [%4];"
                 : "=r"(r[0]), "=r"(r[1]), "=r"(r[2]), "=r"(r[3]) : "r"(addr));
}
__device__ __forceinline__ void ldsm4t(unsigned* r, unsigned addr) {
    asm volatile("ldmatrix.sync.aligned.m8n8.x4.trans.shared.b16 {%0,%1,%2,%3}, [%4];"
                 : "=r"(r[0]), "=r"(r[1]), "=r"(r[2]), "=r"(r[3]) : "r"(addr));
}
__device__ __forceinline__ void mma16816(float* c, const unsigned* a, const unsigned* b) {
    asm volatile(
        "mma.sync.aligned.m16n8k16.row.col.f32.bf16.bf16.f32 "
        "{%0,%1,%2,%3}, {%4,%5,%6,%7}, {%8,%9}, {%0,%1,%2,%3};"
        : "+f"(c[0]), "+f"(c[1]), "+f"(c[2]), "+f"(c[3])
        : "r"(a[0]), "r"(a[1]), "r"(a[2]), "r"(a[3]), "r"(b[0]), "r"(b[1]));
}

// ------------------------------------------------------------------
// Kernel 1: QKV GEMM via bf16 tensor cores (3-term split).
// C[m,n] = sum_k x[b,k,hw(m)] * W[n,k].  M tile 128, N tile 128, BK 32.
// A in smem as [k][m] rows of 272B (ldmatrix.trans); B as [n][k] rows of 80B.
// ------------------------------------------------------------------
#define QA_H 0
#define QA_L 8704
#define QB_H 17408
#define QB_L 27648

__global__ __launch_bounds__(256) void qkv_kernel(
    const float* __restrict__ x, const float* __restrict__ wq,
    const float* __restrict__ bias)
{
    __shared__ __align__(16) char sm[37888];
    const unsigned sb = (unsigned)__cvta_generic_to_shared(sm);

    const int mtile = blockIdx.y;            // 0..783
    const int n0    = blockIdx.x * 128;      // 0,128,256 -> q/k/v
    const int b     = mtile / 98;
    const int hw0   = (mtile - b * 98) * 128;
    const int t     = threadIdx.x;
    const int w     = t >> 5, l = t & 31;
    const int wm    = w >> 1, wn = w & 1;    // warp tile: 32m x 64n

    const float* xb = x + (size_t)b * (CH * HWSZ) + hw0;

    float c[2][8][4];
#pragma unroll
    for (int mf = 0; mf < 2; ++mf)
#pragma unroll
        for (int nf = 0; nf < 8; ++nf)
#pragma unroll
            for (int r = 0; r < 4; ++r) c[mf][nf][r] = 0.f;

    // prefetch regs
    float4 av[4], bv[4];
    const int am4 = (t & 31) * 4;            // m offset for A loads
    const int akr = t >> 5;                  // k row 0..7
    const int bn  = t >> 1;                  // n row for B loads
    const int bko = (t & 1) * 16;            // k offset 0/16

#pragma unroll
    for (int j = 0; j < 4; ++j) {
        av[j] = *(const float4*)(xb + (size_t)(akr + j * 8) * HWSZ + am4);
        bv[j] = *(const float4*)(wq + (size_t)(n0 + bn) * CH + bko + j * 4);
    }

    for (int kt = 0; kt < 4; ++kt) {
        // store prefetched tile to smem (hi/lo split)
#pragma unroll
        for (int j = 0; j < 4; ++j) {
            uint2 hi, lo;
            split4(av[j], hi, lo);
            unsigned ad = sb + QA_H + (akr + j * 8) * 272 + am4 * 2;
            *(uint2*)__cvta_shared_to_generic(ad) = hi;
            *(uint2*)__cvta_shared_to_generic(ad + (QA_L - QA_H)) = lo;
            split4(bv[j], hi, lo);
            unsigned bd = sb + QB_H + bn * 80 + (bko + j * 4) * 2;
            *(uint2*)__cvta_shared_to_generic(bd) = hi;
            *(uint2*)__cvta_shared_to_generic(bd + (QB_L - QB_H)) = lo;
        }
        __syncthreads();
        if (kt < 3) {
#pragma unroll
            for (int j = 0; j < 4; ++j) {
                av[j] = *(const float4*)(xb + (size_t)((kt + 1) * 32 + akr + j * 8) * HWSZ + am4);
                bv[j] = *(const float4*)(wq + (size_t)(n0 + bn) * CH + (kt + 1) * 32 + bko + j * 4);
            }
        }
#pragma unroll
        for (int kb = 0; kb < 32; kb += 16) {
            unsigned ah[2][4], al_[2][4], bh[8][2], bl[8][2];
            const int g = l >> 3, i = l & 7;
#pragma unroll
            for (int mf = 0; mf < 2; ++mf) {
                int row  = kb + i + ((g >> 1) << 3);
                int mcol = wm * 32 + mf * 16 + ((g & 1) << 3);
                unsigned ad = sb + QA_H + row * 272 + mcol * 2;
                ldsm4t(ah[mf], ad);
                ldsm4t(al_[mf], ad + (QA_L - QA_H));
            }
#pragma unroll
            for (int ng = 0; ng < 4; ++ng) {
                int nrow = wn * 64 + ng * 16 + ((g >> 1) << 3) + i;
                unsigned bd = sb + QB_H + nrow * 80 + kb * 2 + ((g & 1) << 4);
                unsigned r[4];
                ldsm4(r, bd);
                bh[ng * 2][0] = r[0]; bh[ng * 2][1] = r[1];
                bh[ng * 2 + 1][0] = r[2]; bh[ng * 2 + 1][1] = r[3];
                ldsm4(r, bd + (QB_L - QB_H));
                bl[ng * 2][0] = r[0]; bl[ng * 2][1] = r[1];
                bl[ng * 2 + 1][0] = r[2]; bl[ng * 2 + 1][1] = r[3];
            }
#pragma unroll
            for (int mf = 0; mf < 2; ++mf)
#pragma unroll
                for (int nf = 0; nf < 8; ++nf) {
                    mma16816(c[mf][nf], ah[mf], bh[nf]);
                    mma16816(c[mf][nf], ah[mf], bl[nf]);
                    mma16816(c[mf][nf], al_[mf], bh[nf]);
                }
        }
        __syncthreads();
    }

    // epilogue: write q/k/v in (b,h,pix,d)
    const int type = n0 >> 7;
    float* dst = (type == 0) ? g_q : (type == 1) ? g_k : g_v;
#pragma unroll
    for (int mf = 0; mf < 2; ++mf)
#pragma unroll
        for (int nf = 0; nf < 8; ++nf) {
            int n = wn * 64 + nf * 8 + (l & 3) * 2;
            int m = wm * 32 + mf * 16 + (l >> 2);
            float b0 = bias[n0 + n], b1 = bias[n0 + n + 1];
            int h = n >> 5, d = n & 31;
            float* hb = dst + ((size_t)(b * NH + h) * HWSZ + hw0) * HD + d;
            float2 o0 = make_float2(c[mf][nf][0] + b0, c[mf][nf][1] + b1);
            float2 o1 = make_float2(c[mf][nf][2] + b0, c[mf][nf][3] + b1);
            *(float2*)&hb[(size_t)m * HD]       = o0;
            *(float2*)&hb[(size_t)(m + 8) * HD] = o1;
        }
}

// ------------------------------------------------------------------
// Kernel 2: dot[b,h,p] = SCALE * sum_d q*k
// ------------------------------------------------------------------
__global__ __launch_bounds__(256) void dot_kernel()
{
    const int bh = blockIdx.y;
    const int t  = blockIdx.x * 256 + threadIdx.x;
    const int p    = t >> 2;
    const int part = t & 3;
    const int base = (bh * HWSZ + p) * HD + part * 8;
    float4 q1 = *(const float4*)&g_q[base];
    float4 q2 = *(const float4*)&g_q[base + 4];
    float4 k1 = *(const float4*)&g_k[base];
    float4 k2 = *(const float4*)&g_k[base + 4];
    float s = q1.x*k1.x + q1.y*k1.y + q1.z*k1.z + q1.w*k1.w
            + q2.x*k2.x + q2.y*k2.y + q2.z*k2.z + q2.w*k2.w;
    s += __shfl_xor_sync(0xffffffffu, s, 1);
    s += __shfl_xor_sync(0xffffffffu, s, 2);
    if (part == 0) g_dot[bh * HWSZ + p] = s * SCALE;
}

// ------------------------------------------------------------------
// Kernel 3: neighborhood attention (circular), unchanged from R2.
// ------------------------------------------------------------------
__global__ __launch_bounds__(256) void attn_kernel(const float* __restrict__ rpb)
{
    __shared__ __align__(16) float ds[22 * 24];
    __shared__ __align__(16) float rs[KK2];
    __shared__ __align__(16) float vs[484 * 20];

    const int bh = blockIdx.z;
    const int h  = bh & 3;
    const int b  = bh >> 2;
    const int y0 = blockIdx.y * 16;
    const int x0 = blockIdx.x * 16;
    const int tid = threadIdx.x;

    for (int idx = tid; idx < 484; idx += 256) {
        int r  = idx / 22, cc = idx - r * 22;
        int gy = y0 + r;  if (gy >= HH) gy -= HH;
        int gx = x0 + cc; if (gx >= WW) gx -= WW;
        ds[r * 24 + cc] = g_dot[bh * HWSZ + gy * WW + gx];
    }
    if (tid < KK2) rs[tid] = rpb[h * KK2 + tid];

    const float* vbase = g_v + (size_t)bh * (HWSZ * HD);

    for (int idx = tid; idx < 484 * 4; idx += 256) {
        int pix = idx >> 2, g = idx & 3;
        int r  = pix / 22, cc = pix - r * 22;
        int gy = y0 + r;  if (gy >= HH) gy -= HH;
        int gx = x0 + cc; if (gx >= WW) gx -= WW;
        *(float4*)&vs[pix * 20 + g * 4] =
            *(const float4*)&vbase[(size_t)(gy * WW + gx) * HD + g * 4];
    }
    __syncthreads();

    const int ty = tid >> 4, tx = tid & 15;

    float wgt[KK2];
    float mx = -1e30f;
#pragma unroll
    for (int i = 0; i < 7; ++i)
#pragma unroll
        for (int j = 0; j < 7; ++j) {
            float val = ds[(ty + i) * 24 + tx + j] + rs[i * 7 + j];
            wgt[i * 7 + j] = val;
            mx = fmaxf(mx, val);
        }
    float sum = 0.f;
#pragma unroll
    for (int n = 0; n < KK2; ++n) { wgt[n] = __expf(wgt[n] - mx); sum += wgt[n]; }
    const float inv = 1.f / sum;

    const int p = (y0 + ty) * WW + (x0 + tx);
    float* obase = g_att + (size_t)(b * HWSZ + p) * CH + h * HD;

    {
        float4 acc[4];
#pragma unroll
        for (int g = 0; g < 4; ++g) acc[g] = make_float4(0.f, 0.f, 0.f, 0.f);
#pragma unroll
        for (int i = 0; i < 7; ++i)
#pragma unroll
            for (int j = 0; j < 7; ++j) {
                float wt  = wgt[i * 7 + j];
                int   pix = (ty + i) * 22 + (tx + j);
#pragma unroll
                for (int g = 0; g < 4; ++g) {
                    float4 vv = *(const float4*)&vs[pix * 20 + g * 4];
                    acc[g].x += wt * vv.x; acc[g].y += wt * vv.y;
                    acc[g].z += wt * vv.z; acc[g].w += wt * vv.w;
                }
            }
#pragma unroll
        for (int g = 0; g < 4; ++g) {
            float4 o = make_float4(acc[g].x*inv, acc[g].y*inv, acc[g].z*inv, acc[g].w*inv);
            *(float4*)&obase[g * 4] = o;
        }
    }
    __syncthreads();

    for (int idx = tid; idx < 484 * 4; idx += 256) {
        int pix = idx >> 2, g = idx & 3;
        int r  = pix / 22, cc = pix - r * 22;
        int gy = y0 + r;  if (gy >= HH) gy -= HH;
        int gx = x0 + cc; if (gx >= WW) gx -= WW;
        *(float4*)&vs[pix * 20 + g * 4] =
            *(const float4*)&vbase[(size_t)(gy * WW + gx) * HD + 16 + g * 4];
    }
    __syncthreads();

    {
        float4 acc[4];
#pragma unroll
        for (int g = 0; g < 4; ++g) acc[g] = make_float4(0.f, 0.f, 0.f, 0.f);
#pragma unroll
        for (int i = 0; i < 7; ++i)
#pragma unroll
            for (int j = 0; j < 7; ++j) {
                float wt  = wgt[i * 7 + j];
                int   pix = (ty + i) * 22 + (tx + j);
#pragma unroll
                for (int g = 0; g < 4; ++g) {
                    float4 vv = *(const float4*)&vs[pix * 20 + g * 4];
                    acc[g].x += wt * vv.x; acc[g].y += wt * vv.y;
                    acc[g].z += wt * vv.z; acc[g].w += wt * vv.w;
                }
            }
#pragma unroll
        for (int g = 0; g < 4; ++g) {
            float4 o = make_float4(acc[g].x*inv, acc[g].y*inv, acc[g].z*inv, acc[g].w*inv);
            *(float4*)&obase[16 + g * 4] = o;
        }
    }
}

// ------------------------------------------------------------------
// Kernel 4: proj GEMM via bf16 tensor cores + smem transpose epilogue.
// A = g_att (k contiguous), B = proj_w. Both stored [row][k] 80B rows.
// ------------------------------------------------------------------
#define PA_H 0
#define PA_L 10240
#define PB_H 20480
#define PB_L 30720

__global__ __launch_bounds__(256) void proj_kernel(
    const float* __restrict__ pw, const float* __restrict__ pb,
    float* __restrict__ out)
{
    __shared__ __align__(16) char sm[40960];
    const unsigned sb = (unsigned)__cvta_generic_to_shared(sm);

    const int mtile = blockIdx.x;
    const int m0    = mtile * 128;
    const int t     = threadIdx.x;
    const int w     = t >> 5, l = t & 31;
    const int wm    = w >> 1, wn = w & 1;

    float c[2][8][4];
#pragma unroll
    for (int mf = 0; mf < 2; ++mf)
#pragma unroll
        for (int nf = 0; nf < 8; ++nf)
#pragma unroll
            for (int r = 0; r < 4; ++r) c[mf][nf][r] = 0.f;

    float4 av[4], bv[4];
    const int rn  = t >> 1;               // row (m for A, n for B)
    const int rko = (t & 1) * 16;

#pragma unroll
    for (int j = 0; j < 4; ++j) {
        av[j] = *(const float4*)(g_att + (size_t)(m0 + rn) * CH + rko + j * 4);
        bv[j] = *(const float4*)(pw + (size_t)rn * CH + rko + j * 4);
    }

    for (int kt = 0; kt < 4; ++kt) {
#pragma unroll
        for (int j = 0; j < 4; ++j) {
            uint2 hi, lo;
            split4(av[j], hi, lo);
            unsigned ad = sb + PA_H + rn * 80 + (rko + j * 4) * 2;
            *(uint2*)__cvta_shared_to_generic(ad) = hi;
            *(uint2*)__cvta_shared_to_generic(ad + (PA_L - PA_H)) = lo;
            split4(bv[j], hi, lo);
            unsigned bd = sb + PB_H + rn * 80 + (rko + j * 4) * 2;
            *(uint2*)__cvta_shared_to_generic(bd) = hi;
            *(uint2*)__cvta_shared_to_generic(bd + (PB_L - PB_H)) = lo;
        }
        __syncthreads();
        if (kt < 3) {
#pragma unroll
            for (int j = 0; j < 4; ++j) {
                av[j] = *(const float4*)(g_att + (size_t)(m0 + rn) * CH + (kt + 1) * 32 + rko + j * 4);
                bv[j] = *(const float4*)(pw + (size_t)rn * CH + (kt + 1) * 32 + rko + j * 4);
            }
        }
#pragma unroll
        for (int kb = 0; kb < 32; kb += 16) {
            unsigned ah[2][4], al_[2][4], bh[8][2], bl[8][2];
            const int g = l >> 3, i = l & 7;
#pragma unroll
            for (int mf = 0; mf < 2; ++mf) {
                int mrow = wm * 32 + mf * 16 + ((g & 1) << 3) + i;
                unsigned ad = sb + PA_H + mrow * 80 + kb * 2 + ((g >> 1) << 4);
                ldsm4(ah[mf], ad);
                ldsm4(al_[mf], ad + (PA_L - PA_H));
            }
#pragma unroll
            for (int ng = 0; ng < 4; ++ng) {
                int nrow = wn * 64 + ng * 16 + ((g >> 1) << 3) + i;
                unsigned bd = sb + PB_H + nrow * 80 + kb * 2 + ((g & 1) << 4);
                unsigned r[4];
                ldsm4(r, bd);
                bh[ng * 2][0] = r[0]; bh[ng * 2][1] = r[1];
                bh[ng * 2 + 1][0] = r[2]; bh[ng * 2 + 1][1] = r[3];
                ldsm4(r, bd + (PB_L - PB_H));
                bl[ng * 2][0] = r[0]; bl[ng * 2][1] = r[1];
                bl[ng * 2 + 1][0] = r[2]; bl[ng * 2 + 1][1] = r[3];
            }
#pragma unroll
            for (int mf = 0; mf < 2; ++mf)
#pragma unroll
                for (int nf = 0; nf < 8; ++nf) {
                    mma16816(c[mf][nf], ah[mf], bh[nf]);
                    mma16816(c[mf][nf], ah[mf], bl[nf]);
                    mma16816(c[mf][nf], al_[mf], bh[nf]);
                }
        }
        __syncthreads();
    }

    // epilogue: smem transpose in 4 chunks of 32 n-channels
    const int b   = mtile / 98;
    const int hw0 = (mtile - b * 98) * 128;
    float* eb = (float*)sm;   // [32][132]

    for (int nc = 0; nc < 4; ++nc) {
        if (wn == (nc >> 1)) {
            int nfbase = (nc & 1) * 4;
#pragma unroll
            for (int mf = 0; mf < 2; ++mf)
#pragma unroll
                for (int nf2 = 0; nf2 < 4; ++nf2) {
                    int nf = nfbase + nf2;
                    int nl = wn * 64 + nf * 8 + (l & 3) * 2 - nc * 32;
                    int m  = wm * 32 + mf * 16 + (l >> 2);
                    eb[nl * 132 + m]             = c[mf][nf][0];
                    eb[(nl + 1) * 132 + m]       = c[mf][nf][1];
                    eb[nl * 132 + m + 8]         = c[mf][nf][2];
                    eb[(nl + 1) * 132 + m + 8]   = c[mf][nf][3];
                }
        }
        __syncthreads();
        {
            int nl = t >> 3;              // 0..31
            int mm = (t & 7) * 16;        // 4 float4
            int ng = nc * 32 + nl;
            float bias = pb[ng];
            float* orow = out + (size_t)(b * CH + ng) * HWSZ + hw0;
#pragma unroll
            for (int j = 0; j < 4; ++j) {
                float4 v = *(float4*)&eb[nl * 132 + mm + j * 4];
                v.x += bias; v.y += bias; v.z += bias; v.w += bias;
                *(float4*)&orow[mm + j * 4] = v;
            }
        }
        __syncthreads();
    }
}

// ------------------------------------------------------------------
extern "C" void kernel_launch(void* const* d_in, const int* in_sizes, int n_in,
                              void* d_out, int out_size)
{
    const float* x      = (const float*)d_in[0];
    const float* qkv_w  = (const float*)d_in[1];
    const float* qkv_b  = (const float*)d_in[2];
    const float* rpb    = (const float*)d_in[3];
    const float* proj_w = (const float*)d_in[4];
    const float* proj_b = (const float*)d_in[5];
    float* out = (float*)d_out;

    qkv_kernel<<<dim3(3, 784), 256>>>(x, qkv_w, qkv_b);
    dot_kernel<<<dim3(196, 32), 256>>>();
    attn_kernel<<<dim3(7, 7, 32), 256>>>(rpb);
    proj_kernel<<<784, 256>>>(proj_w, proj_b, out);
}

// round 4
// speedup vs baseline: 1.5703x; 1.2056x over previous
#include <cuda_runtime.h>
#include <cuda_bf16.h>

#define BATCH 8
#define CH    128
#define HH    112
#define WW    112
#define HWSZ  12544     // 112*112
#define NH    4
#define HD    32
#define KS    7
#define KK2   49
#define SCALE 0.17677669529663687f   // 32^-0.5

// Scratch (static device allocations; no cudaMalloc allowed).
static __device__ __align__(16) float g_v  [BATCH*NH*HWSZ*HD];   // (b,h,p,d)
static __device__ __align__(16) float g_dot[BATCH*NH*HWSZ];      // (b,h,p)
static __device__ __align__(16) float g_att[BATCH*HWSZ*CH];      // (b,p,c)  c = h*32+d

// ---------------- helpers: bf16 split + ldmatrix + mma -------------

__device__ __forceinline__ unsigned bfpack(__nv_bfloat16 a, __nv_bfloat16 b) {
    return (unsigned)__bfloat16_as_ushort(a) | ((unsigned)__bfloat16_as_ushort(b) << 16);
}

__device__ __forceinline__ void split4(float4 v, uint2& hi, uint2& lo) {
    __nv_bfloat16 hx = __float2bfloat16(v.x);
    __nv_bfloat16 hy = __float2bfloat16(v.y);
    __nv_bfloat16 hz = __float2bfloat16(v.z);
    __nv_bfloat16 hw = __float2bfloat16(v.w);
    __nv_bfloat16 lx = __float2bfloat16(v.x - __bfloat162float(hx));
    __nv_bfloat16 ly = __float2bfloat16(v.y - __bfloat162float(hy));
    __nv_bfloat16 lz = __float2bfloat16(v.z - __bfloat162float(hz));
    __nv_bfloat16 lw = __float2bfloat16(v.w - __bfloat162float(hw));
    hi.x = bfpack(hx, hy); hi.y = bfpack(hz, hw);
    lo.x = bfpack(lx, ly); lo.y = bfpack(lz, lw);
}

__device__ __forceinline__ void ldsm4(unsigned* r, unsigned addr) {
    asm volatile("ldmatrix.sync.aligned.m8n8.x4.shared.b16 {%0,%1,%2,%3}, [%4];"
                 : "=r"(r[0]), "=r"(r[1]), "=r"(r[2]), "=r"(r[3]) : "r"(addr));
}
__device__ __forceinline__ void ldsm4t(unsigned* r, unsigned addr) {
    asm volatile("ldmatrix.sync.aligned.m8n8.x4.trans.shared.b16 {%0,%1,%2,%3}, [%4];"
                 : "=r"(r[0]), "=r"(r[1]), "=r"(r[2]), "=r"(r[3]) : "r"(addr));
}
__device__ __forceinline__ void mma16816(float* c, const unsigned* a, const unsigned* b) {
    asm volatile(
        "mma.sync.aligned.m16n8k16.row.col.f32.bf16.bf16.f32 "
        "{%0,%1,%2,%3}, {%4,%5,%6,%7}, {%8,%9}, {%0,%1,%2,%3};"
        : "+f"(c[0]), "+f"(c[1]), "+f"(c[2]), "+f"(c[3])
        : "r"(a[0]), "r"(a[1]), "r"(a[2]), "r"(a[3]), "r"(b[0]), "r"(b[1]));
}

// ------------------------------------------------------------------
// Kernel 1: fused QKV GEMM + q.k dot.
// Per CTA: m-tile of 128 pixels. Full split A (x tile, [128k][128m] bf16
// hi/lo, 272B rows) resident in smem; B (weights) streamed per (nt,kt),
// double-buffered. nt = 0(q) stash, 1(k) -> dot, 2(v) -> g_v.
// 512 threads, warp grid 4m x 4n, warp tile 32x32.
// ------------------------------------------------------------------
#define QAF_H 0
#define QAF_L 34816
#define QBT   69632
#define QBUF  20480
#define QQS   110592
#define QSMEM 178176

__global__ __launch_bounds__(512) void qkvdot_kernel(
    const float* __restrict__ x, const float* __restrict__ wq,
    const float* __restrict__ bias)
{
    extern __shared__ __align__(16) char sm[];
    const unsigned sb = (unsigned)__cvta_generic_to_shared(sm);
    float* qstash = (float*)(sm + QQS);     // [128m][132]

    const int mtile = blockIdx.x;            // 0..783
    const int b     = mtile / 98;
    const int hw0   = (mtile - b * 98) * 128;
    const int t     = threadIdx.x;
    const int l     = t & 31, w = t >> 5;
    const int wm    = w >> 2, wn = w & 3;
    const int g     = l >> 3, i = l & 7;

    const float* xb = x + (size_t)b * (CH * HWSZ) + hw0;

    // ---- prologue: load full A (x tile), prefetch first B chunk ----
    const int m4 = (t & 31) * 4;
    const int kr = t >> 5;                   // 0..15
    float4 av[8];
#pragma unroll
    for (int j = 0; j < 8; ++j)
        av[j] = *(const float4*)(xb + (size_t)(kr + j * 16) * HWSZ + m4);

    const int bn  = t >> 2;                  // 0..127
    const int bko = (t & 3) * 8;             // 0,8,16,24
    float4 bv[2];
    bv[0] = *(const float4*)(wq + (size_t)bn * CH + bko);
    bv[1] = *(const float4*)(wq + (size_t)bn * CH + bko + 4);

#pragma unroll
    for (int j = 0; j < 8; ++j) {
        uint2 hi, lo;
        split4(av[j], hi, lo);
        unsigned ad = sb + QAF_H + (kr + j * 16) * 272 + m4 * 2;
        *(uint2*)__cvta_shared_to_generic(ad) = hi;
        *(uint2*)__cvta_shared_to_generic(ad + (QAF_L - QAF_H)) = lo;
    }
    {
        unsigned bd = sb + QBT + bn * 80 + bko * 2;
        uint2 hi, lo;
        split4(bv[0], hi, lo);
        *(uint2*)__cvta_shared_to_generic(bd) = hi;
        *(uint2*)__cvta_shared_to_generic(bd + 10240) = lo;
        split4(bv[1], hi, lo);
        *(uint2*)__cvta_shared_to_generic(bd + 8) = hi;
        *(uint2*)__cvta_shared_to_generic(bd + 10240 + 8) = lo;
    }
    __syncthreads();

    float c[2][4][4];
#pragma unroll
    for (int mf = 0; mf < 2; ++mf)
#pragma unroll
        for (int nf = 0; nf < 4; ++nf)
#pragma unroll
            for (int r2 = 0; r2 < 4; ++r2) c[mf][nf][r2] = 0.f;

    for (int it = 0; it < 12; ++it) {
        const int nt = it >> 2, kt = it & 3, buf = it & 1;

        if (it < 11) {
            const int it2 = it + 1;
            const float* wp = wq + (size_t)(((it2 >> 2) * 128) + bn) * CH
                              + (it2 & 3) * 32 + bko;
            bv[0] = *(const float4*)wp;
            bv[1] = *(const float4*)(wp + 4);
        }

        const unsigned Bb = sb + QBT + buf * QBUF;
#pragma unroll
        for (int kb = 0; kb < 32; kb += 16) {
            unsigned ah[2][4], al_[2][4], bh[4][2], bl[4][2];
#pragma unroll
            for (int mf = 0; mf < 2; ++mf) {
                int row  = kt * 32 + kb + i + ((g >> 1) << 3);
                int mcol = wm * 32 + mf * 16 + ((g & 1) << 3);
                unsigned ad = sb + QAF_H + row * 272 + mcol * 2;
                ldsm4t(ah[mf], ad);
                ldsm4t(al_[mf], ad + (QAF_L - QAF_H));
            }
#pragma unroll
            for (int ng = 0; ng < 2; ++ng) {
                int nrow = wn * 32 + ng * 16 + ((g >> 1) << 3) + i;
                unsigned bd = Bb + nrow * 80 + kb * 2 + ((g & 1) << 4);
                unsigned r[4];
                ldsm4(r, bd);
                bh[ng * 2][0] = r[0]; bh[ng * 2][1] = r[1];
                bh[ng * 2 + 1][0] = r[2]; bh[ng * 2 + 1][1] = r[3];
                ldsm4(r, bd + 10240);
                bl[ng * 2][0] = r[0]; bl[ng * 2][1] = r[1];
                bl[ng * 2 + 1][0] = r[2]; bl[ng * 2 + 1][1] = r[3];
            }
#pragma unroll
            for (int mf = 0; mf < 2; ++mf)
#pragma unroll
                for (int nf = 0; nf < 4; ++nf) {
                    mma16816(c[mf][nf], ah[mf], bh[nf]);
                    mma16816(c[mf][nf], ah[mf], bl[nf]);
                    mma16816(c[mf][nf], al_[mf], bh[nf]);
                }
        }

        if (it < 11) {
            unsigned bd = sb + QBT + (buf ^ 1) * QBUF + bn * 80 + bko * 2;
            uint2 hi, lo;
            split4(bv[0], hi, lo);
            *(uint2*)__cvta_shared_to_generic(bd) = hi;
            *(uint2*)__cvta_shared_to_generic(bd + 10240) = lo;
            split4(bv[1], hi, lo);
            *(uint2*)__cvta_shared_to_generic(bd + 8) = hi;
            *(uint2*)__cvta_shared_to_generic(bd + 10240 + 8) = lo;
        }

        if (kt == 3) {
            if (nt == 0) {
                // q epilogue: stash q+bias in smem fp32
#pragma unroll
                for (int mf = 0; mf < 2; ++mf)
#pragma unroll
                    for (int nf = 0; nf < 4; ++nf) {
                        int n = wn * 32 + nf * 8 + (l & 3) * 2;
                        int m = wm * 32 + mf * 16 + (l >> 2);
                        float b0 = bias[n], b1 = bias[n + 1];
                        qstash[m * 132 + n]           = c[mf][nf][0] + b0;
                        qstash[m * 132 + n + 1]       = c[mf][nf][1] + b1;
                        qstash[(m + 8) * 132 + n]     = c[mf][nf][2] + b0;
                        qstash[(m + 8) * 132 + n + 1] = c[mf][nf][3] + b1;
                    }
            } else if (nt == 1) {
                // k epilogue: dot = SCALE * sum_d q*k, per head (head == wn)
#pragma unroll
                for (int mf = 0; mf < 2; ++mf) {
                    float s0 = 0.f, s1 = 0.f;
                    int m = wm * 32 + mf * 16 + (l >> 2);
#pragma unroll
                    for (int nf = 0; nf < 4; ++nf) {
                        int n = wn * 32 + nf * 8 + (l & 3) * 2;
                        float b0 = bias[128 + n], b1 = bias[128 + n + 1];
                        float2 q0 = *(float2*)&qstash[m * 132 + n];
                        float2 q1 = *(float2*)&qstash[(m + 8) * 132 + n];
                        s0 += (c[mf][nf][0] + b0) * q0.x + (c[mf][nf][1] + b1) * q0.y;
                        s1 += (c[mf][nf][2] + b0) * q1.x + (c[mf][nf][3] + b1) * q1.y;
                    }
                    s0 += __shfl_xor_sync(0xffffffffu, s0, 1);
                    s0 += __shfl_xor_sync(0xffffffffu, s0, 2);
                    s1 += __shfl_xor_sync(0xffffffffu, s1, 1);
                    s1 += __shfl_xor_sync(0xffffffffu, s1, 2);
                    if ((l & 3) == 0) {
                        size_t base = (size_t)(b * NH + wn) * HWSZ + hw0;
                        g_dot[base + m]     = s0 * SCALE;
                        g_dot[base + m + 8] = s1 * SCALE;
                    }
                }
            } else {
                // v epilogue: write g_v (b,h,p,d), head == wn
#pragma unroll
                for (int mf = 0; mf < 2; ++mf)
#pragma unroll
                    for (int nf = 0; nf < 4; ++nf) {
                        int n = wn * 32 + nf * 8 + (l & 3) * 2;
                        int m = wm * 32 + mf * 16 + (l >> 2);
                        float b0 = bias[256 + n], b1 = bias[256 + n + 1];
                        int d = n & 31;
                        float* hb = g_v + ((size_t)(b * NH + wn) * HWSZ + hw0) * HD + d;
                        *(float2*)&hb[(size_t)m * HD] =
                            make_float2(c[mf][nf][0] + b0, c[mf][nf][1] + b1);
                        *(float2*)&hb[(size_t)(m + 8) * HD] =
                            make_float2(c[mf][nf][2] + b0, c[mf][nf][3] + b1);
                    }
            }
#pragma unroll
            for (int mf = 0; mf < 2; ++mf)
#pragma unroll
                for (int nf = 0; nf < 4; ++nf)
#pragma unroll
                    for (int r2 = 0; r2 < 4; ++r2) c[mf][nf][r2] = 0.f;
        }
        __syncthreads();
    }
}

// ------------------------------------------------------------------
// Kernel 2: neighborhood attention (circular). Unchanged from R3.
// ------------------------------------------------------------------
__global__ __launch_bounds__(256) void attn_kernel(const float* __restrict__ rpb)
{
    __shared__ __align__(16) float ds[22 * 24];
    __shared__ __align__(16) float rs[KK2];
    __shared__ __align__(16) float vs[484 * 20];

    const int bh = blockIdx.z;
    const int h  = bh & 3;
    const int b  = bh >> 2;
    const int y0 = blockIdx.y * 16;
    const int x0 = blockIdx.x * 16;
    const int tid = threadIdx.x;

    for (int idx = tid; idx < 484; idx += 256) {
        int r  = idx / 22, cc = idx - r * 22;
        int gy = y0 + r;  if (gy >= HH) gy -= HH;
        int gx = x0 + cc; if (gx >= WW) gx -= WW;
        ds[r * 24 + cc] = g_dot[bh * HWSZ + gy * WW + gx];
    }
    if (tid < KK2) rs[tid] = rpb[h * KK2 + tid];

    const float* vbase = g_v + (size_t)bh * (HWSZ * HD);

    for (int idx = tid; idx < 484 * 4; idx += 256) {
        int pix = idx >> 2, gg = idx & 3;
        int r  = pix / 22, cc = pix - r * 22;
        int gy = y0 + r;  if (gy >= HH) gy -= HH;
        int gx = x0 + cc; if (gx >= WW) gx -= WW;
        *(float4*)&vs[pix * 20 + gg * 4] =
            *(const float4*)&vbase[(size_t)(gy * WW + gx) * HD + gg * 4];
    }
    __syncthreads();

    const int ty = tid >> 4, tx = tid & 15;

    float wgt[KK2];
    float mx = -1e30f;
#pragma unroll
    for (int i = 0; i < 7; ++i)
#pragma unroll
        for (int j = 0; j < 7; ++j) {
            float val = ds[(ty + i) * 24 + tx + j] + rs[i * 7 + j];
            wgt[i * 7 + j] = val;
            mx = fmaxf(mx, val);
        }
    float sum = 0.f;
#pragma unroll
    for (int n = 0; n < KK2; ++n) { wgt[n] = __expf(wgt[n] - mx); sum += wgt[n]; }
    const float inv = 1.f / sum;

    const int p = (y0 + ty) * WW + (x0 + tx);
    float* obase = g_att + (size_t)(b * HWSZ + p) * CH + h * HD;

    {
        float4 acc[4];
#pragma unroll
        for (int gg = 0; gg < 4; ++gg) acc[gg] = make_float4(0.f, 0.f, 0.f, 0.f);
#pragma unroll
        for (int i = 0; i < 7; ++i)
#pragma unroll
            for (int j = 0; j < 7; ++j) {
                float wt  = wgt[i * 7 + j];
                int   pix = (ty + i) * 22 + (tx + j);
#pragma unroll
                for (int gg = 0; gg < 4; ++gg) {
                    float4 vv = *(const float4*)&vs[pix * 20 + gg * 4];
                    acc[gg].x += wt * vv.x; acc[gg].y += wt * vv.y;
                    acc[gg].z += wt * vv.z; acc[gg].w += wt * vv.w;
                }
            }
#pragma unroll
        for (int gg = 0; gg < 4; ++gg) {
            float4 o = make_float4(acc[gg].x*inv, acc[gg].y*inv, acc[gg].z*inv, acc[gg].w*inv);
            *(float4*)&obase[gg * 4] = o;
        }
    }
    __syncthreads();

    for (int idx = tid; idx < 484 * 4; idx += 256) {
        int pix = idx >> 2, gg = idx & 3;
        int r  = pix / 22, cc = pix - r * 22;
        int gy = y0 + r;  if (gy >= HH) gy -= HH;
        int gx = x0 + cc; if (gx >= WW) gx -= WW;
        *(float4*)&vs[pix * 20 + gg * 4] =
            *(const float4*)&vbase[(size_t)(gy * WW + gx) * HD + 16 + gg * 4];
    }
    __syncthreads();

    {
        float4 acc[4];
#pragma unroll
        for (int gg = 0; gg < 4; ++gg) acc[gg] = make_float4(0.f, 0.f, 0.f, 0.f);
#pragma unroll
        for (int i = 0; i < 7; ++i)
#pragma unroll
            for (int j = 0; j < 7; ++j) {
                float wt  = wgt[i * 7 + j];
                int   pix = (ty + i) * 22 + (tx + j);
#pragma unroll
                for (int gg = 0; gg < 4; ++gg) {
                    float4 vv = *(const float4*)&vs[pix * 20 + gg * 4];
                    acc[gg].x += wt * vv.x; acc[gg].y += wt * vv.y;
                    acc[gg].z += wt * vv.z; acc[gg].w += wt * vv.w;
                }
            }
#pragma unroll
        for (int gg = 0; gg < 4; ++gg) {
            float4 o = make_float4(acc[gg].x*inv, acc[gg].y*inv, acc[gg].z*inv, acc[gg].w*inv);
            *(float4*)&obase[16 + gg * 4] = o;
        }
    }
}

// ------------------------------------------------------------------
// Kernel 3: proj GEMM + transpose. Full split B (weights) resident;
// A (g_att) streamed per kt, double-buffered. 512 threads, 4x4 warps.
// ------------------------------------------------------------------
#define PBF_H 0
#define PBF_L 34816
#define PAT   69632
#define PBUF  20480
#define PSMEM 110592

__global__ __launch_bounds__(512) void proj_kernel(
    const float* __restrict__ pw, const float* __restrict__ pb,
    float* __restrict__ out)
{
    extern __shared__ __align__(16) char sm[];
    const unsigned sb = (unsigned)__cvta_generic_to_shared(sm);

    const int mtile = blockIdx.x;
    const int m0    = mtile * 128;
    const int t     = threadIdx.x;
    const int l     = t & 31, w = t >> 5;
    const int wm    = w >> 2, wn = w & 3;
    const int g     = l >> 3, i = l & 7;

    // ---- prologue: full B, first A chunk ----
    const int rn = t >> 2;                 // 0..127
    const int kq = t & 3;
    {
        float4 bload[8];
#pragma unroll
        for (int j = 0; j < 8; ++j)
            bload[j] = *(const float4*)(pw + (size_t)rn * CH + kq * 32 + j * 4);
#pragma unroll
        for (int j = 0; j < 8; ++j) {
            uint2 hi, lo;
            split4(bload[j], hi, lo);
            unsigned bd = sb + PBF_H + rn * 272 + (kq * 32 + j * 4) * 2;
            *(uint2*)__cvta_shared_to_generic(bd) = hi;
            *(uint2*)__cvta_shared_to_generic(bd + (PBF_L - PBF_H)) = lo;
        }
    }
    const int ako = (t & 3) * 8;
    float4 av[2];
    av[0] = *(const float4*)(g_att + (size_t)(m0 + rn) * CH + ako);
    av[1] = *(const float4*)(g_att + (size_t)(m0 + rn) * CH + ako + 4);
    {
        unsigned ad = sb + PAT + rn * 80 + ako * 2;
        uint2 hi, lo;
        split4(av[0], hi, lo);
        *(uint2*)__cvta_shared_to_generic(ad) = hi;
        *(uint2*)__cvta_shared_to_generic(ad + 10240) = lo;
        split4(av[1], hi, lo);
        *(uint2*)__cvta_shared_to_generic(ad + 8) = hi;
        *(uint2*)__cvta_shared_to_generic(ad + 10240 + 8) = lo;
    }
    __syncthreads();

    float c[2][4][4];
#pragma unroll
    for (int mf = 0; mf < 2; ++mf)
#pragma unroll
        for (int nf = 0; nf < 4; ++nf)
#pragma unroll
            for (int r2 = 0; r2 < 4; ++r2) c[mf][nf][r2] = 0.f;

    for (int kt = 0; kt < 4; ++kt) {
        const int buf = kt & 1;
        if (kt < 3) {
            const float* ap = g_att + (size_t)(m0 + rn) * CH + (kt + 1) * 32 + ako;
            av[0] = *(const float4*)ap;
            av[1] = *(const float4*)(ap + 4);
        }
        const unsigned Ab = sb + PAT + buf * PBUF;
#pragma unroll
        for (int kb = 0; kb < 32; kb += 16) {
            unsigned ah[2][4], al_[2][4], bh[4][2], bl[4][2];
#pragma unroll
            for (int mf = 0; mf < 2; ++mf) {
                int mrow = wm * 32 + mf * 16 + ((g & 1) << 3) + i;
                unsigned ad = Ab + mrow * 80 + kb * 2 + ((g >> 1) << 4);
                ldsm4(ah[mf], ad);
                ldsm4(al_[mf], ad + 10240);
            }
#pragma unroll
            for (int ng = 0; ng < 2; ++ng) {
                int nrow = wn * 32 + ng * 16 + ((g >> 1) << 3) + i;
                unsigned bd = sb + PBF_H + nrow * 272 + (kt * 32 + kb) * 2 + ((g & 1) << 4);
                unsigned r[4];
                ldsm4(r, bd);
                bh[ng * 2][0] = r[0]; bh[ng * 2][1] = r[1];
                bh[ng * 2 + 1][0] = r[2]; bh[ng * 2 + 1][1] = r[3];
                ldsm4(r, bd + (PBF_L - PBF_H));
                bl[ng * 2][0] = r[0]; bl[ng * 2][1] = r[1];
                bl[ng * 2 + 1][0] = r[2]; bl[ng * 2 + 1][1] = r[3];
            }
#pragma unroll
            for (int mf = 0; mf < 2; ++mf)
#pragma unroll
                for (int nf = 0; nf < 4; ++nf) {
                    mma16816(c[mf][nf], ah[mf], bh[nf]);
                    mma16816(c[mf][nf], ah[mf], bl[nf]);
                    mma16816(c[mf][nf], al_[mf], bh[nf]);
                }
        }
        if (kt < 3) {
            unsigned ad = sb + PAT + (buf ^ 1) * PBUF + rn * 80 + ako * 2;
            uint2 hi, lo;
            split4(av[0], hi, lo);
            *(uint2*)__cvta_shared_to_generic(ad) = hi;
            *(uint2*)__cvta_shared_to_generic(ad + 10240) = lo;
            split4(av[1], hi, lo);
            *(uint2*)__cvta_shared_to_generic(ad + 8) = hi;
            *(uint2*)__cvta_shared_to_generic(ad + 10240 + 8) = lo;
        }
        __syncthreads();
    }

    // ---- epilogue: smem transpose, 4 chunks of 32 channels ----
    const int b   = mtile / 98;
    const int hw0 = (mtile - b * 98) * 128;
    float* eb = (float*)sm;   // reuse B region: [32][132]

    for (int nc = 0; nc < 4; ++nc) {
        if (wn == nc) {
#pragma unroll
            for (int mf = 0; mf < 2; ++mf)
#pragma unroll
                for (int nf = 0; nf < 4; ++nf) {
                    int nl = nf * 8 + (l & 3) * 2;
                    int m  = wm * 32 + mf * 16 + (l >> 2);
                    eb[nl * 132 + m]           = c[mf][nf][0];
                    eb[(nl + 1) * 132 + m]     = c[mf][nf][1];
                    eb[nl * 132 + m + 8]       = c[mf][nf][2];
                    eb[(nl + 1) * 132 + m + 8] = c[mf][nf][3];
                }
        }
        __syncthreads();
        {
            int nl = t >> 4;              // 0..31
            int mm = (t & 15) * 8;        // 2 float4
            int ng2 = nc * 32 + nl;
            float bias = pb[ng2];
            float* orow = out + (size_t)(b * CH + ng2) * HWSZ + hw0;
#pragma unroll
            for (int j = 0; j < 2; ++j) {
                float4 v = *(float4*)&eb[nl * 132 + mm + j * 4];
                v.x += bias; v.y += bias; v.z += bias; v.w += bias;
                *(float4*)&orow[mm + j * 4] = v;
            }
        }
        __syncthreads();
    }
}

// ------------------------------------------------------------------
extern "C" void kernel_launch(void* const* d_in, const int* in_sizes, int n_in,
                              void* d_out, int out_size)
{
    const float* x      = (const float*)d_in[0];
    const float* qkv_w  = (const float*)d_in[1];
    const float* qkv_b  = (const float*)d_in[2];
    const float* rpb    = (const float*)d_in[3];
    const float* proj_w = (const float*)d_in[4];
    const float* proj_b = (const float*)d_in[5];
    float* out = (float*)d_out;

    cudaFuncSetAttribute(qkvdot_kernel,
                         cudaFuncAttributeMaxDynamicSharedMemorySize, QSMEM);
    cudaFuncSetAttribute(proj_kernel,
                         cudaFuncAttributeMaxDynamicSharedMemorySize, PSMEM);

    qkvdot_kernel<<<784, 512, QSMEM>>>(x, qkv_w, qkv_b);
    attn_kernel<<<dim3(7, 7, 32), 256>>>(rpb);
    proj_kernel<<<784, 512, PSMEM>>>(proj_w, proj_b, out);
}